// round 11
// baseline (speedup 1.0000x reference)
#include <cuda_runtime.h>
#include <cuda_bf16.h>

#define N_SRC_C   100000
#define N_DST_C   50000
#define N_EDGES_C 800000
#define DD        64

// W transposed: Wt[k*64 + j] = W[j*128 + k]
__device__ float g_Wt[128 * 64];

// Packed f32x2 helpers (sm_103a)
#define FMA2(d, a, bb) \
    asm("fma.rn.f32x2 %0, %1, %2, %3;" : "=l"(d) : "l"(a), "l"(bb), "l"(d))
#define PACKDUP(o, x) \
    asm("mov.b64 %0, {%1, %1};" : "=l"(o) : "f"(x))

// ---------------------------------------------------------------------------
// Kernel 1: transpose W into g_Wt (coalesced read, strided write).
// No scratch zeroing needed anymore.
// ---------------------------------------------------------------------------
__global__ void prep_kernel(const float* __restrict__ W) {
    int i = blockIdx.x * blockDim.x + threadIdx.x;
    if (i < 128 * 64) {
        int jj = i >> 7;        // W row  (0..63)
        int k  = i & 127;       // W col  (0..127)
        g_Wt[k * 64 + jj] = __ldg(W + i);
    }
}

// ---------------------------------------------------------------------------
// Kernel 2 (agg + neigh fused, atomic-free):
// One 16-lane group per dst row. dst_idx is sorted, so the row's edges are
// [lower_bound(r), lower_bound(r+1)). Each lane owns a float4 column slice,
// accumulates the gathered H_src rows in registers, then writes
// out2 = 0.9*HBar + 0.1*mean directly (coalesced 256B per group).
// ---------------------------------------------------------------------------
__global__ void __launch_bounds__(256)
agg_kernel(const float* __restrict__ H_src,
           const int*   __restrict__ src_idx,
           const int*   __restrict__ dst_idx,
           const float* __restrict__ HBar,
           float* __restrict__ out2) {
    int t    = threadIdx.x;
    int lane = t & 15;                       // float4 column index
    int r    = blockIdx.x * 16 + (t >> 4);   // dst row (grid covers exactly)
    unsigned gmask = 0xFFFFu << (t & 16);    // this 16-lane group's mask

    // lower_bound(r) and lower_bound(r+1) in sorted dst_idx (redundant per
    // lane; all lanes hit the same lines -> broadcast sectors).
    int lo;
    {
        int a = 0, bnd = N_EDGES_C;
        while (a < bnd) {
            int m = (a + bnd) >> 1;
            if (__ldg(dst_idx + m) < r) a = m + 1; else bnd = m;
        }
        lo = a;
    }
    int hi;
    {
        int a = lo, bnd = N_EDGES_C;
        while (a < bnd) {
            int m = (a + bnd) >> 1;
            if (__ldg(dst_idx + m) < r + 1) a = m + 1; else bnd = m;
        }
        hi = a;
    }
    int deg = hi - lo;

    float4 acc = make_float4(0.f, 0.f, 0.f, 0.f);

    for (int base = lo; base < hi; base += 16) {
        int e = base + lane;
        int sidx = (e < hi) ? __ldg(src_idx + e) : 0;
        int cnt = hi - base;
        if (cnt >= 16) {
            #pragma unroll
            for (int j = 0; j < 16; j++) {
                int s = __shfl_sync(gmask, sidx, j, 16);
                float4 v = __ldg((const float4*)(H_src + (size_t)s * DD) + lane);
                acc.x += v.x; acc.y += v.y; acc.z += v.z; acc.w += v.w;
            }
        } else {
            for (int j = 0; j < cnt; j++) {
                int s = __shfl_sync(gmask, sidx, j, 16);
                float4 v = __ldg((const float4*)(H_src + (size_t)s * DD) + lane);
                acc.x += v.x; acc.y += v.y; acc.z += v.z; acc.w += v.w;
            }
        }
    }

    float inv = 0.1f / fmaxf((float)deg, 1.f);
    float4 hb = __ldg((const float4*)(HBar + (size_t)r * DD) + lane);
    float4 o;
    o.x = 0.9f * hb.x + inv * acc.x;
    o.y = 0.9f * hb.y + inv * acc.y;
    o.z = 0.9f * hb.z + inv * acc.z;
    o.w = 0.9f * hb.w + inv * acc.w;
    reinterpret_cast<float4*>(out2 + (size_t)r * DD)[lane] = o;
}

// ---------------------------------------------------------------------------
// Kernel 3: h = relu([H_dst, out2] @ W^T + b)  — the R4-measured version
// (4 rows x 4 cols per thread, f32x2 FMA, conflict-free LDS.128 of k-major W)
// with __launch_bounds__(256,4) to lift occupancy from 3 to 4 blocks/SM.
// ---------------------------------------------------------------------------
__global__ void __launch_bounds__(256, 4)
gemm_kernel(const float* __restrict__ H_dst,
            const float* __restrict__ out2,
            const float* __restrict__ b,
            float* __restrict__ out) {
    __shared__ float ws[128 * 64];

    int t = threadIdx.x;
    #pragma unroll
    for (int i = 0; i < 8; i++) {
        int idx = t + i * 256;
        reinterpret_cast<float4*>(ws)[idx] =
            __ldg(reinterpret_cast<const float4*>(g_Wt) + idx);
    }
    __syncthreads();

    int tx = t & 15;
    int ty = t >> 4;
    int j0 = tx * 4;
    int r0 = (blockIdx.x << 6) + ty * 4;

    const float* xr[4];
    const float* yr[4];
    #pragma unroll
    for (int m = 0; m < 4; m++) {
        int row = min(r0 + m, N_DST_C - 1);
        xr[m] = H_dst + (size_t)row * DD;
        yr[m] = out2  + (size_t)row * DD;
    }

    unsigned long long acc[4][2];
    #pragma unroll
    for (int r = 0; r < 4; r++) { acc[r][0] = 0ull; acc[r][1] = 0ull; }

    // First half: k = 0..63 over H_dst
    #pragma unroll 4
    for (int k = 0; k < 64; k += 4) {
        float4 xa[4];
        #pragma unroll
        for (int m = 0; m < 4; m++)
            xa[m] = __ldg((const float4*)(xr[m] + k));
        #pragma unroll
        for (int kk = 0; kk < 4; kk++) {
            ulonglong2 w2 = *reinterpret_cast<const ulonglong2*>(
                ws + (k + kk) * 64 + j0);
            #pragma unroll
            for (int r = 0; r < 4; r++) {
                float xs = reinterpret_cast<const float*>(&xa[r])[kk];
                unsigned long long xx;
                PACKDUP(xx, xs);
                FMA2(acc[r][0], xx, w2.x);
                FMA2(acc[r][1], xx, w2.y);
            }
        }
    }
    // Second half: k = 64..127 over h_neigh (out2)
    #pragma unroll 4
    for (int k = 0; k < 64; k += 4) {
        float4 xa[4];
        #pragma unroll
        for (int m = 0; m < 4; m++)
            xa[m] = __ldg((const float4*)(yr[m] + k));
        #pragma unroll
        for (int kk = 0; kk < 4; kk++) {
            ulonglong2 w2 = *reinterpret_cast<const ulonglong2*>(
                ws + (k + 64 + kk) * 64 + j0);
            #pragma unroll
            for (int r = 0; r < 4; r++) {
                float xs = reinterpret_cast<const float*>(&xa[r])[kk];
                unsigned long long xx;
                PACKDUP(xx, xs);
                FMA2(acc[r][0], xx, w2.x);
                FMA2(acc[r][1], xx, w2.y);
            }
        }
    }

    float bb[4];
    #pragma unroll
    for (int j = 0; j < 4; j++) bb[j] = __ldg(b + j0 + j);

    #pragma unroll
    for (int m = 0; m < 4; m++) {
        int row = r0 + m;
        if (row < N_DST_C) {
            float2 p0 = *reinterpret_cast<float2*>(&acc[m][0]);
            float2 p1 = *reinterpret_cast<float2*>(&acc[m][1]);
            float4 o;
            o.x = fmaxf(p0.x + bb[0], 0.f);
            o.y = fmaxf(p0.y + bb[1], 0.f);
            o.z = fmaxf(p1.x + bb[2], 0.f);
            o.w = fmaxf(p1.y + bb[3], 0.f);
            *reinterpret_cast<float4*>(out + (size_t)row * DD + j0) = o;
        }
    }
}

// ---------------------------------------------------------------------------
// Launch
// ---------------------------------------------------------------------------
extern "C" void kernel_launch(void* const* d_in, const int* in_sizes, int n_in,
                              void* d_out, int out_size) {
    const float* H_src   = (const float*)d_in[0];
    const float* H_dst   = (const float*)d_in[1];
    const float* HBar    = (const float*)d_in[2];
    const int*   src_idx = (const int*)  d_in[3];
    const int*   dst_idx = (const int*)  d_in[4];
    const float* W       = (const float*)d_in[5];
    const float* b       = (const float*)d_in[6];

    float* out  = (float*)d_out;                    // h:       [N_DST, 64]
    float* out2 = out + (size_t)N_DST_C * DD;       // h_neigh: [N_DST, 64]

    prep_kernel<<<32, 256>>>(W);
    agg_kernel<<<N_DST_C / 16, 256>>>(H_src, src_idx, dst_idx, HBar, out2);
    gemm_kernel<<<(N_DST_C + 63) / 64, 256>>>(H_dst, out2, b, out);
}

// round 15
// speedup vs baseline: 1.2566x; 1.2566x over previous
#include <cuda_runtime.h>
#include <cuda_bf16.h>

#define N_SRC_C   100000
#define N_DST_C   50000
#define N_EDGES_C 800000
#define DD        64

// W transposed: Wt[k*64 + j] = W[j*128 + k]
__device__ float g_Wt[128 * 64];
// rowptr[r] = first edge index e with dst_idx[e] >= r;  rowptr[N_DST] = N_EDGES
__device__ int g_rowptr[N_DST_C + 1];

// Packed f32x2 helpers (sm_103a)
#define FMA2(d, a, bb) \
    asm("fma.rn.f32x2 %0, %1, %2, %3;" : "=l"(d) : "l"(a), "l"(bb), "l"(d))
#define PACKDUP(o, x) \
    asm("mov.b64 %0, {%1, %1};" : "=l"(o) : "f"(x))

// ---------------------------------------------------------------------------
// Kernel 1: W transpose + rowptr scatter (one linear pass over sorted dst_idx;
// a thread at each segment boundary writes rowptr for the gap rows).
// ---------------------------------------------------------------------------
__global__ void prep_kernel(const float* __restrict__ W,
                            const int*   __restrict__ dst_idx) {
    int i = blockIdx.x * blockDim.x + threadIdx.x;
    if (i < 128 * 64) {
        int jj = i >> 7;        // W row  (0..63)
        int k  = i & 127;       // W col  (0..127)
        g_Wt[k * 64 + jj] = __ldg(W + i);
    }
    if (i < N_EDGES_C) {
        int d     = __ldg(dst_idx + i);
        int dprev = (i == 0) ? -1 : __ldg(dst_idx + i - 1);
        for (int r = dprev + 1; r <= d; r++)
            g_rowptr[r] = i;
        if (i == N_EDGES_C - 1)
            for (int r = d + 1; r <= N_DST_C; r++)
                g_rowptr[r] = N_EDGES_C;
    }
}

// ---------------------------------------------------------------------------
// Kernel 2 (agg + neigh fused, atomic-free, O(1) range lookup):
// One 16-lane group per dst row; edges [rowptr[r], rowptr[r+1]).
// Each lane owns a float4 column slice, accumulates the gathered H_src rows
// in registers, then writes out2 = 0.9*HBar + 0.1*mean (coalesced 256B).
// ---------------------------------------------------------------------------
__global__ void __launch_bounds__(256)
agg_kernel(const float* __restrict__ H_src,
           const int*   __restrict__ src_idx,
           const float* __restrict__ HBar,
           float* __restrict__ out2) {
    int t    = threadIdx.x;
    int lane = t & 15;                       // float4 column index
    int r    = blockIdx.x * 16 + (t >> 4);   // dst row (grid covers exactly)
    unsigned gmask = 0xFFFFu << (t & 16);    // this 16-lane group's mask

    int lo = __ldg(g_rowptr + r);
    int hi = __ldg(g_rowptr + r + 1);
    int deg = hi - lo;

    float4 acc = make_float4(0.f, 0.f, 0.f, 0.f);

    for (int base = lo; base < hi; base += 16) {
        int e = base + lane;
        int sidx = (e < hi) ? __ldg(src_idx + e) : 0;
        int cnt = hi - base;
        if (cnt >= 16) {
            #pragma unroll
            for (int j = 0; j < 16; j++) {
                int s = __shfl_sync(gmask, sidx, j, 16);
                float4 v = __ldg((const float4*)(H_src + (size_t)s * DD) + lane);
                acc.x += v.x; acc.y += v.y; acc.z += v.z; acc.w += v.w;
            }
        } else {
            for (int j = 0; j < cnt; j++) {
                int s = __shfl_sync(gmask, sidx, j, 16);
                float4 v = __ldg((const float4*)(H_src + (size_t)s * DD) + lane);
                acc.x += v.x; acc.y += v.y; acc.z += v.z; acc.w += v.w;
            }
        }
    }

    float inv = 0.1f / fmaxf((float)deg, 1.f);
    float4 hb = __ldg((const float4*)(HBar + (size_t)r * DD) + lane);
    float4 o;
    o.x = 0.9f * hb.x + inv * acc.x;
    o.y = 0.9f * hb.y + inv * acc.y;
    o.z = 0.9f * hb.z + inv * acc.z;
    o.w = 0.9f * hb.w + inv * acc.w;
    reinterpret_cast<float4*>(out2 + (size_t)r * DD)[lane] = o;
}

// ---------------------------------------------------------------------------
// Kernel 3: h = relu([H_dst, out2] @ W^T + b)  — the R4-measured inner loop
// (4 rows x 4 cols per thread, f32x2 FMA, conflict-free LDS.128 of k-major W)
// with __launch_bounds__(256,4) to lift occupancy from 3 to 4 blocks/SM.
// ---------------------------------------------------------------------------
__global__ void __launch_bounds__(256, 4)
gemm_kernel(const float* __restrict__ H_dst,
            const float* __restrict__ out2,
            const float* __restrict__ b,
            float* __restrict__ out) {
    __shared__ float ws[128 * 64];

    int t = threadIdx.x;
    #pragma unroll
    for (int i = 0; i < 8; i++) {
        int idx = t + i * 256;
        reinterpret_cast<float4*>(ws)[idx] =
            __ldg(reinterpret_cast<const float4*>(g_Wt) + idx);
    }
    __syncthreads();

    int tx = t & 15;
    int ty = t >> 4;
    int j0 = tx * 4;
    int r0 = (blockIdx.x << 6) + ty * 4;

    const float* xr[4];
    const float* yr[4];
    #pragma unroll
    for (int m = 0; m < 4; m++) {
        int row = min(r0 + m, N_DST_C - 1);
        xr[m] = H_dst + (size_t)row * DD;
        yr[m] = out2  + (size_t)row * DD;
    }

    unsigned long long acc[4][2];
    #pragma unroll
    for (int r = 0; r < 4; r++) { acc[r][0] = 0ull; acc[r][1] = 0ull; }

    // First half: k = 0..63 over H_dst
    #pragma unroll 4
    for (int k = 0; k < 64; k += 4) {
        float4 xa[4];
        #pragma unroll
        for (int m = 0; m < 4; m++)
            xa[m] = __ldg((const float4*)(xr[m] + k));
        #pragma unroll
        for (int kk = 0; kk < 4; kk++) {
            ulonglong2 w2 = *reinterpret_cast<const ulonglong2*>(
                ws + (k + kk) * 64 + j0);
            #pragma unroll
            for (int r = 0; r < 4; r++) {
                float xs = reinterpret_cast<const float*>(&xa[r])[kk];
                unsigned long long xx;
                PACKDUP(xx, xs);
                FMA2(acc[r][0], xx, w2.x);
                FMA2(acc[r][1], xx, w2.y);
            }
        }
    }
    // Second half: k = 64..127 over h_neigh (out2)
    #pragma unroll 4
    for (int k = 0; k < 64; k += 4) {
        float4 xa[4];
        #pragma unroll
        for (int m = 0; m < 4; m++)
            xa[m] = __ldg((const float4*)(yr[m] + k));
        #pragma unroll
        for (int kk = 0; kk < 4; kk++) {
            ulonglong2 w2 = *reinterpret_cast<const ulonglong2*>(
                ws + (k + 64 + kk) * 64 + j0);
            #pragma unroll
            for (int r = 0; r < 4; r++) {
                float xs = reinterpret_cast<const float*>(&xa[r])[kk];
                unsigned long long xx;
                PACKDUP(xx, xs);
                FMA2(acc[r][0], xx, w2.x);
                FMA2(acc[r][1], xx, w2.y);
            }
        }
    }

    float bb[4];
    #pragma unroll
    for (int j = 0; j < 4; j++) bb[j] = __ldg(b + j0 + j);

    #pragma unroll
    for (int m = 0; m < 4; m++) {
        int row = r0 + m;
        if (row < N_DST_C) {
            float2 p0 = *reinterpret_cast<float2*>(&acc[m][0]);
            float2 p1 = *reinterpret_cast<float2*>(&acc[m][1]);
            float4 o;
            o.x = fmaxf(p0.x + bb[0], 0.f);
            o.y = fmaxf(p0.y + bb[1], 0.f);
            o.z = fmaxf(p1.x + bb[2], 0.f);
            o.w = fmaxf(p1.y + bb[3], 0.f);
            *reinterpret_cast<float4*>(out + (size_t)row * DD + j0) = o;
        }
    }
}

// ---------------------------------------------------------------------------
// Launch
// ---------------------------------------------------------------------------
extern "C" void kernel_launch(void* const* d_in, const int* in_sizes, int n_in,
                              void* d_out, int out_size) {
    const float* H_src   = (const float*)d_in[0];
    const float* H_dst   = (const float*)d_in[1];
    const float* HBar    = (const float*)d_in[2];
    const int*   src_idx = (const int*)  d_in[3];
    const int*   dst_idx = (const int*)  d_in[4];
    const float* W       = (const float*)d_in[5];
    const float* b       = (const float*)d_in[6];

    float* out  = (float*)d_out;                    // h:       [N_DST, 64]
    float* out2 = out + (size_t)N_DST_C * DD;       // h_neigh: [N_DST, 64]

    prep_kernel<<<(N_EDGES_C + 255) / 256, 256>>>(W, dst_idx);
    agg_kernel<<<N_DST_C / 16, 256>>>(H_src, src_idx, HBar, out2);
    gemm_kernel<<<(N_DST_C + 63) / 64, 256>>>(H_dst, out2, b, out);
}